// round 12
// baseline (speedup 1.0000x reference)
#include <cuda_runtime.h>
#include <cuda_fp16.h>
#include <cstdint>

// ---------------- Problem constants ----------------
#define BATCH 256
#define TLEN  500
#define IDIM  1024
#define ODIM  2048
#define TEFF  (TLEN - 1)            // 499
#define MEFF  (BATCH * TEFF)

// ---------------- Tiling ----------------
#define BM 128
#define BN 128
#define BK 32
#define NITER (IDIM / BK)           // 32
#define NCHUNK 4                    // 128,128,128,115
#define ROWP  (BK + 8)              // padded row stride in halves (40)
#define ABUF_BYTES (BM * ROWP * 2)         // 10240 (fp16 A, double-buffered)
#define B_BASE_OFF (2 * ABUF_BYTES)        // 20480
#define B_STAGE_BYTES (BN * ROWP * 2)      // 10240 (double-buffered)
#define H_OFF (B_BASE_OFF + 2 * B_STAGE_BYTES)   // 40960
#define ROWPH 132                   // fp32 h/acc tile row stride (words)
#define SMEM_TOTAL (H_OFF + BM * ROWPH * 4)      // 108544 (occ 2: 217K < 227K)

// ---------------- Scratch ----------------
__device__ __align__(256) __half g_Bh[(size_t)ODIM * IDIM];  // ~4 MB (L2-resident)

// ---------------- PTX helpers ----------------
__device__ __forceinline__ uint32_t smem_u32(const void* p) {
    uint32_t a;
    asm("{ .reg .u64 t; cvta.to.shared.u64 t, %1; cvt.u32.u64 %0, t; }" : "=r"(a) : "l"(p));
    return a;
}
__device__ __forceinline__ void cp_async16(uint32_t dst, const void* src) {
    asm volatile("cp.async.cg.shared.global [%0], [%1], 16;" :: "r"(dst), "l"(src));
}
__device__ __forceinline__ void cp_commit() {
    asm volatile("cp.async.commit_group;" ::: "memory");
}
__device__ __forceinline__ void sts64(uint32_t addr, uint32_t lo, uint32_t hi) {
    asm volatile("st.shared.v2.u32 [%0], {%1, %2};" :: "r"(addr), "r"(lo), "r"(hi) : "memory");
}
__device__ __forceinline__ void ldmatrix_x4(uint32_t& r0, uint32_t& r1, uint32_t& r2, uint32_t& r3,
                                            uint32_t addr) {
    asm volatile("ldmatrix.sync.aligned.m8n8.x4.shared.b16 {%0,%1,%2,%3}, [%4];"
                 : "=r"(r0), "=r"(r1), "=r"(r2), "=r"(r3) : "r"(addr));
}
// fp16-accumulate HMMA: D,C are 2 b32 regs (4 halves)
__device__ __forceinline__ void mma_16816_f16(uint32_t& c0, uint32_t& c1,
                                              uint32_t a0, uint32_t a1, uint32_t a2, uint32_t a3,
                                              uint32_t b0, uint32_t b1) {
    asm volatile(
        "mma.sync.aligned.m16n8k16.row.col.f16.f16.f16.f16 "
        "{%0,%1}, {%2,%3,%4,%5}, {%6,%7}, {%0,%1};"
        : "+r"(c0), "+r"(c1)
        : "r"(a0), "r"(a1), "r"(a2), "r"(a3), "r"(b0), "r"(b1));
}

// ---------------- w conversion ----------------
__global__ __launch_bounds__(256) void convert_w_kernel(const float* __restrict__ w) {
    const size_t idx = (size_t)blockIdx.x * 256 + threadIdx.x;  // k*ODIM + n
    const int k = (int)(idx >> 11);
    const int n = (int)(idx & (ODIM - 1));
    g_Bh[(size_t)n * IDIM + k] = __float2half_rn(w[idx]);
}

// ---------------- Fused GEMM + scan ----------------
extern __shared__ __half smem[];

// A: fp32 LDG (128x32 tile, 4 float4/thread), predicated
__device__ __forceinline__ void ldg_a(const float* __restrict__ x, int b, int t0, int rows,
                                      int k0, int tid, float4 (&v)[4]) {
#pragma unroll
    for (int q = 0; q < 4; q++) {
        const int f = q * 256 + tid;
        const int r = f >> 3, c = f & 7;
        float4 t = make_float4(0.f, 0.f, 0.f, 0.f);
        if (r < rows)
            t = *(const float4*)(x + ((size_t)(b * TLEN + t0 + r)) * IDIM + k0 + c * 4);
        v[q] = t;
    }
}
__device__ __forceinline__ void sts_a(uint32_t abuf, int tid, const float4 (&v)[4]) {
#pragma unroll
    for (int q = 0; q < 4; q++) {
        const int f = q * 256 + tid;
        const int r = f >> 3, c = f & 7;
        __half2 h0 = __float22half2_rn(make_float2(v[q].x, v[q].y));
        __half2 h1 = __float22half2_rn(make_float2(v[q].z, v[q].w));
        sts64(abuf + (r * ROWP + c * 4) * 2, *(uint32_t*)&h0, *(uint32_t*)&h1);
    }
}
__device__ __forceinline__ void load_b_stage(int tid, int n0, int kidx, int stage,
                                             uint32_t sbase) {
    const uint32_t sB = sbase + B_BASE_OFF + stage * B_STAGE_BYTES;
    const int k0 = kidx * BK;
#pragma unroll
    for (int q = 0; q < 2; q++) {
        int idx = tid + q * 256;
        int r = idx >> 2, c = idx & 3;
        const void* g = (const void*)(g_Bh + (size_t)(n0 + r) * IDIM + k0 + c * 8);
        cp_async16(sB + (r * ROWP + c * 8) * 2, g);
    }
}

__global__ __launch_bounds__(256, 2)
void synaptic_fused_kernel(const float* __restrict__ x,
                           float* __restrict__ out,
                           const float* __restrict__ alpha,
                           const float* __restrict__ beta) {
    const int tid = threadIdx.x;
    const int wid = tid >> 5;
    const int lane = tid & 31;
    const int warp_m = wid & 1;      // 2 warps along M (64 rows)
    const int warp_n = wid >> 1;     // 4 warps along N (32 cols)
    const int n0 = blockIdx.x * BN;
    const int b  = blockIdx.y;

    const uint32_t sbase = smem_u32(smem);
    float* hs32 = (float*)((char*)smem + H_OFF);

    float decay = 0.f, syn = 0.f;
    if (tid < BN) {
        const int o = n0 + tid;
        decay = alpha[o] * (1.0f - beta[o]);
    }

    const int lrow = lane & 15;
    const int lk   = (lane >> 4) * 8;
    const uint32_t a_lane = (uint32_t)((warp_m * 64 + lrow) * ROWP + lk) * 2;
    const uint32_t b_lane = (uint32_t)((warp_n * 32 + lrow) * ROWP + lk) * 2;
    const int r_lo = lane >> 2;
    const int c_lo = (lane & 3) * 2;

    float4 av[4];

    // ---- prologue for chunk 0 ----
    ldg_a(x, b, 0, BM, 0, tid, av);
    sts_a(sbase, tid, av);
    load_b_stage(tid, n0, 0, 0, sbase);
    cp_commit();

    for (int ch = 0; ch < NCHUNK; ch++) {
        const int t0 = ch * BM;
        const int rows = (TEFF - t0 < BM) ? (TEFF - t0) : BM;  // 128,128,128,115

        uint32_t hacc[4][4][2];    // fp16 accumulators (4 halves per frag)
#pragma unroll
        for (int i = 0; i < 4; i++)
#pragma unroll
            for (int j = 0; j < 4; j++)
                hacc[i][j][0] = hacc[i][j][1] = 0u;

        for (int it = 0; it < NITER; it++) {
            asm volatile("cp.async.wait_group 0;" ::: "memory");
            __syncthreads();

            const bool nxt = (it + 1 < NITER);
            if (nxt) {
                ldg_a(x, b, t0, rows, (it + 1) * BK, tid, av);
                load_b_stage(tid, n0, it + 1, (it + 1) & 1, sbase);
            }
            cp_commit();

            const uint32_t sa = sbase + (it & 1) * ABUF_BYTES + a_lane;
            const uint32_t sb = sbase + B_BASE_OFF + (it & 1) * B_STAGE_BYTES + b_lane;

#pragma unroll
            for (int kk = 0; kk < BK; kk += 16) {
                uint32_t a[4][4], bm[2][4];
#pragma unroll
                for (int mt = 0; mt < 4; mt++)
                    ldmatrix_x4(a[mt][0], a[mt][1], a[mt][2], a[mt][3],
                                sa + (mt * 16 * ROWP + kk) * 2);
#pragma unroll
                for (int np = 0; np < 2; np++)
                    ldmatrix_x4(bm[np][0], bm[np][1], bm[np][2], bm[np][3],
                                sb + (np * 16 * ROWP + kk) * 2);
#pragma unroll
                for (int mt = 0; mt < 4; mt++) {
#pragma unroll
                    for (int nt = 0; nt < 4; nt++) {
                        const int np = nt >> 1, odd = nt & 1;
                        mma_16816_f16(hacc[mt][nt][0], hacc[mt][nt][1],
                                      a[mt][0], a[mt][1], a[mt][2], a[mt][3],
                                      bm[np][odd], bm[np][2 + odd]);
                    }
                }
            }

            if (nxt) sts_a(sbase + ((it + 1) & 1) * ABUF_BYTES, tid, av);

            // ---- promote fp16 chains into fp32 smem tile every 8 iterations ----
            if ((it & 7) == 7) {
                const bool first = (it == 7);
#pragma unroll
                for (int mt = 0; mt < 4; mt++) {
#pragma unroll
                    for (int nt = 0; nt < 4; nt++) {
#pragma unroll
                        for (int half = 0; half < 2; half++) {
                            float2 v = __half22float2(
                                *(__half2*)&hacc[mt][nt][half]);
                            const int row = warp_m * 64 + mt * 16 + r_lo + half * 8;
                            float* p = hs32 + (size_t)row * ROWPH
                                       + warp_n * 32 + nt * 8 + c_lo;
                            if (first) {
                                p[0] = v.x; p[1] = v.y;
                            } else {
                                p[0] += v.x; p[1] += v.y;
                            }
                            hacc[mt][nt][half] = 0u;
                        }
                    }
                }
            }
        }
        __syncthreads();   // fp32 h tile complete & visible

        // ---- prologue for next chunk BEFORE the scan (overlap DMA with scan) ----
        if (ch + 1 < NCHUNK) {
            const int nt0 = (ch + 1) * BM;
            const int nrows = (TEFF - nt0 < BM) ? (TEFF - nt0) : BM;
            ldg_a(x, b, nt0, nrows, 0, tid, av);
            sts_a(sbase, tid, av);
            load_b_stage(tid, n0, 0, 0, sbase);
            cp_commit();
        }

        // ---- column-parallel scan (warps 0-3); others park at next barrier ----
        if (tid < BN) {
            float* obase = out + (size_t)b * TLEN * ODIM + n0 + tid;
            if (ch == 0) obase[0] = 0.0f;
#pragma unroll 4
            for (int t = 0; t < rows; t++) {
                float h = hs32[(size_t)t * ROWPH + tid];
                syn = fmaf(decay, syn, h);
                obase[(size_t)(t0 + t + 1) * ODIM] = syn;
            }
        }
        // next chunk's iter-0 barrier orders h-tile reuse (first promote is at it=7)
    }
}

// ---------------- Launch ----------------
extern "C" void kernel_launch(void* const* d_in, const int* in_sizes, int n_in,
                              void* d_out, int out_size) {
    const float* x     = (const float*)d_in[0];
    const float* w     = (const float*)d_in[1];
    const float* alpha = (const float*)d_in[2];
    const float* beta  = (const float*)d_in[3];
    float* out = (float*)d_out;

    cudaFuncSetAttribute(synaptic_fused_kernel, cudaFuncAttributeMaxDynamicSharedMemorySize,
                         SMEM_TOTAL);

    convert_w_kernel<<<(IDIM * ODIM) / 256, 256>>>(w);
    synaptic_fused_kernel<<<dim3(ODIM / BN, BATCH), 256, SMEM_TOTAL>>>(x, out, alpha, beta);
}

// round 13
// speedup vs baseline: 1.8366x; 1.8366x over previous
#include <cuda_runtime.h>
#include <cuda_fp16.h>
#include <cstdint>

// ---------------- Problem constants ----------------
#define BATCH 256
#define TLEN  500
#define IDIM  1024
#define ODIM  2048
#define TEFF  (TLEN - 1)            // 499
#define MEFF  (BATCH * TEFF)

// ---------------- Tiling ----------------
#define BM 128
#define BN 128
#define BK 32
#define NST 4                       // combined A+B stage depth
#define NITER (IDIM / BK)           // 32
#define NCHUNK 4                    // 128,128,128,115
#define ROWP  (BK + 8)              // padded row stride in halves (40)
#define A_STAGE_BYTES (BM * ROWP * 2)      // 10240
#define B_STAGE_BYTES (BN * ROWP * 2)      // 10240
#define STAGE_BYTES (A_STAGE_BYTES + B_STAGE_BYTES)  // 20480
#define H_OFF (NST * STAGE_BYTES)          // 81920
#define ROWPH 132                   // h-tile row stride (halves)
#define SMEM_TOTAL (H_OFF + BM * ROWPH * 2)  // 115712 (occ 2: 231424 < 232448)

// ---------------- Scratch ----------------
__device__ __align__(256) __half g_Ah[(size_t)MEFF * IDIM];  // ~262 MB
__device__ __align__(256) __half g_Bh[(size_t)ODIM * IDIM];  // ~4 MB (L2-resident)

// ---------------- PTX helpers ----------------
__device__ __forceinline__ uint32_t smem_u32(const void* p) {
    uint32_t a;
    asm("{ .reg .u64 t; cvta.to.shared.u64 t, %1; cvt.u32.u64 %0, t; }" : "=r"(a) : "l"(p));
    return a;
}
__device__ __forceinline__ void cp_async16(uint32_t dst, const void* src) {
    asm volatile("cp.async.cg.shared.global [%0], [%1], 16;" :: "r"(dst), "l"(src));
}
__device__ __forceinline__ void cp_commit() {
    asm volatile("cp.async.commit_group;" ::: "memory");
}
__device__ __forceinline__ void ldmatrix_x4(uint32_t& r0, uint32_t& r1, uint32_t& r2, uint32_t& r3,
                                            uint32_t addr) {
    asm volatile("ldmatrix.sync.aligned.m8n8.x4.shared.b16 {%0,%1,%2,%3}, [%4];"
                 : "=r"(r0), "=r"(r1), "=r"(r2), "=r"(r3) : "r"(addr));
}
__device__ __forceinline__ void mma_16816(float& c0, float& c1, float& c2, float& c3,
                                          uint32_t a0, uint32_t a1, uint32_t a2, uint32_t a3,
                                          uint32_t b0, uint32_t b1) {
    asm volatile(
        "mma.sync.aligned.m16n8k16.row.col.f32.f16.f16.f32 "
        "{%0,%1,%2,%3}, {%4,%5,%6,%7}, {%8,%9}, {%0,%1,%2,%3};"
        : "+f"(c0), "+f"(c1), "+f"(c2), "+f"(c3)
        : "r"(a0), "r"(a1), "r"(a2), "r"(a3), "r"(b0), "r"(b1));
}

// ---------------- Conversion kernels ----------------
// x [B,T,I] f32 -> g_Ah [MEFF][IDIM] fp16, row = b*TEFF + t (t < TEFF)
__global__ __launch_bounds__(256) void convert_x_kernel(const float* __restrict__ x) {
    const int row = blockIdx.x;
    const int b = row / TEFF;
    const int t = row - b * TEFF;
    const float4 v = ((const float4*)(x + ((size_t)(b * TLEN + t)) * IDIM))[threadIdx.x];
    __half2 h01 = __float22half2_rn(make_float2(v.x, v.y));
    __half2 h23 = __float22half2_rn(make_float2(v.z, v.w));
    uint2 pk;
    pk.x = *(uint32_t*)&h01;
    pk.y = *(uint32_t*)&h23;
    *(uint2*)(g_Ah + (size_t)row * IDIM + threadIdx.x * 4) = pk;
}

// w [I,O] f32 -> g_Bh [ODIM][IDIM] fp16 (K-major / transposed)
__global__ __launch_bounds__(256) void convert_w_kernel(const float* __restrict__ w) {
    const size_t idx = (size_t)blockIdx.x * 256 + threadIdx.x;  // k*ODIM + n
    const int k = (int)(idx >> 11);
    const int n = (int)(idx & (ODIM - 1));
    g_Bh[(size_t)n * IDIM + k] = __float2half_rn(w[idx]);
}

// ---------------- Fused GEMM + scan ----------------
extern __shared__ __half smem[];

// Combined stage: A (row-clamped; tail rows duplicate valid data, never read
// by the scan) + B, all cp.async, 4 x 16B per thread.
__device__ __forceinline__ void load_stage(int tid, int b, int t0, int rows, int n0,
                                           int kidx, int stage, uint32_t sbase) {
    const uint32_t sA = sbase + stage * STAGE_BYTES;
    const uint32_t sB = sA + A_STAGE_BYTES;
    const int k0 = kidx * BK;
#pragma unroll
    for (int q = 0; q < 2; q++) {
        int idx = tid + q * 256;
        int r = idx >> 2, c = idx & 3;
        int rc = (r < rows) ? r : (rows - 1);          // clamp: stay in-bounds
        const void* g = (const void*)(g_Ah + (size_t)(b * TEFF + t0 + rc) * IDIM + k0 + c * 8);
        cp_async16(sA + (r * ROWP + c * 8) * 2, g);
    }
#pragma unroll
    for (int q = 0; q < 2; q++) {
        int idx = tid + q * 256;
        int r = idx >> 2, c = idx & 3;
        const void* g = (const void*)(g_Bh + (size_t)(n0 + r) * IDIM + k0 + c * 8);
        cp_async16(sB + (r * ROWP + c * 8) * 2, g);
    }
}

__global__ __launch_bounds__(256, 2)
void synaptic_fused_kernel(float* __restrict__ out,
                           const float* __restrict__ alpha,
                           const float* __restrict__ beta) {
    const int tid = threadIdx.x;
    const int wid = tid >> 5;
    const int lane = tid & 31;
    const int warp_m = wid & 1;      // 2 warps along M (64 rows)
    const int warp_n = wid >> 1;     // 4 warps along N (32 cols)
    const int n0 = blockIdx.x * BN;
    const int b  = blockIdx.y;

    const uint32_t sbase = smem_u32(smem);
    __half* hs16 = (__half*)((char*)smem + H_OFF);

    float decay = 0.f, syn = 0.f;
    if (tid < BN) {
        const int o = n0 + tid;
        decay = alpha[o] * (1.0f - beta[o]);
    }

    const int lrow = lane & 15;
    const int lk   = (lane >> 4) * 8;
    const uint32_t a_lane = (uint32_t)((warp_m * 64 + lrow) * ROWP + lk) * 2;
    const uint32_t b_lane = (uint32_t)((warp_n * 32 + lrow) * ROWP + lk) * 2
                            + (uint32_t)A_STAGE_BYTES;
    const int r_lo = lane >> 2;
    const int c_lo = (lane & 3) * 2;

    // ---- prologue for chunk 0: stages 0..2 ----
#pragma unroll
    for (int s = 0; s < NST - 1; s++) {
        load_stage(tid, b, 0, BM, n0, s, s, sbase);
        cp_commit();
    }

    for (int ch = 0; ch < NCHUNK; ch++) {
        const int t0 = ch * BM;
        const int rows = (TEFF - t0 < BM) ? (TEFF - t0) : BM;  // 128,128,128,115

        float acc[4][4][4];
#pragma unroll
        for (int i = 0; i < 4; i++)
#pragma unroll
            for (int j = 0; j < 4; j++)
#pragma unroll
                for (int f = 0; f < 4; f++) acc[i][j][f] = 0.f;

        for (int it = 0; it < NITER; it++) {
            asm volatile("cp.async.wait_group %0;" :: "n"(NST - 2) : "memory");
            __syncthreads();

            if (it + NST - 1 < NITER) {
                int kidx = it + NST - 1;
                load_stage(tid, b, t0, rows, n0, kidx, kidx & (NST - 1), sbase);
            }
            cp_commit();

            const uint32_t sa = sbase + (it & (NST - 1)) * STAGE_BYTES + a_lane;
            const uint32_t sb = sbase + (it & (NST - 1)) * STAGE_BYTES + b_lane;

            // ---- batch ALL fragment loads for the iteration ----
            uint32_t a[2][4][4], bm[2][2][4];
#pragma unroll
            for (int kk2 = 0; kk2 < 2; kk2++) {
#pragma unroll
                for (int mt = 0; mt < 4; mt++)
                    ldmatrix_x4(a[kk2][mt][0], a[kk2][mt][1], a[kk2][mt][2], a[kk2][mt][3],
                                sa + (mt * 16 * ROWP + kk2 * 16) * 2);
#pragma unroll
                for (int np = 0; np < 2; np++)
                    ldmatrix_x4(bm[kk2][np][0], bm[kk2][np][1], bm[kk2][np][2], bm[kk2][np][3],
                                sb + (np * 16 * ROWP + kk2 * 16) * 2);
            }
            // ---- then all 32 MMAs ----
#pragma unroll
            for (int kk2 = 0; kk2 < 2; kk2++) {
#pragma unroll
                for (int mt = 0; mt < 4; mt++) {
#pragma unroll
                    for (int nt = 0; nt < 4; nt++) {
                        const int np = nt >> 1, odd = nt & 1;
                        mma_16816(acc[mt][nt][0], acc[mt][nt][1], acc[mt][nt][2], acc[mt][nt][3],
                                  a[kk2][mt][0], a[kk2][mt][1], a[kk2][mt][2], a[kk2][mt][3],
                                  bm[kk2][np][odd], bm[kk2][np][2 + odd]);
                    }
                }
            }
        }

        // ---- write h tile (fp16) to dedicated smem ----
#pragma unroll
        for (int mt = 0; mt < 4; mt++) {
#pragma unroll
            for (int half = 0; half < 2; half++) {
                const int row = warp_m * 64 + mt * 16 + r_lo + half * 8;
                __half* dst = hs16 + (size_t)row * ROWPH + warp_n * 32 + c_lo;
#pragma unroll
                for (int nt = 0; nt < 4; nt++) {
                    __half2 hv = __float22half2_rn(
                        make_float2(acc[mt][nt][half * 2 + 0], acc[mt][nt][half * 2 + 1]));
                    *(__half2*)(dst + nt * 8) = hv;
                }
            }
        }
        __syncthreads();   // h visible; pipeline buffers free

        // ---- prologue for next chunk BEFORE the scan (overlap DMA with scan) ----
        if (ch + 1 < NCHUNK) {
            const int nt0 = (ch + 1) * BM;
            const int nrows = (TEFF - nt0 < BM) ? (TEFF - nt0) : BM;
#pragma unroll
            for (int s = 0; s < NST - 1; s++) {
                load_stage(tid, b, nt0, nrows, n0, s, s, sbase);
                cp_commit();
            }
        }

        // ---- column-parallel scan (warps 0-3); others park at next barrier ----
        if (tid < BN) {
            float* obase = out + (size_t)b * TLEN * ODIM + n0 + tid;
            if (ch == 0) obase[0] = 0.0f;
#pragma unroll 4
            for (int t = 0; t < rows; t++) {
                float h = __half2float(hs16[(size_t)t * ROWPH + tid]);
                syn = fmaf(decay, syn, h);
                obase[(size_t)(t0 + t + 1) * ODIM] = syn;
            }
        }
        // next chunk's iter-0 wait+barrier orders everything
    }
}

// ---------------- Launch ----------------
extern "C" void kernel_launch(void* const* d_in, const int* in_sizes, int n_in,
                              void* d_out, int out_size) {
    const float* x     = (const float*)d_in[0];
    const float* w     = (const float*)d_in[1];
    const float* alpha = (const float*)d_in[2];
    const float* beta  = (const float*)d_in[3];
    float* out = (float*)d_out;

    cudaFuncSetAttribute(synaptic_fused_kernel, cudaFuncAttributeMaxDynamicSharedMemorySize,
                         SMEM_TOTAL);

    convert_w_kernel<<<(IDIM * ODIM) / 256, 256>>>(w);
    convert_x_kernel<<<MEFF, 256>>>(x);
    synaptic_fused_kernel<<<dim3(ODIM / BN, BATCH), 256, SMEM_TOTAL>>>(out, alpha, beta);
}

// round 14
// speedup vs baseline: 2.0514x; 1.1170x over previous
#include <cuda_runtime.h>
#include <cuda_fp16.h>
#include <cstdint>

// ---------------- Problem constants ----------------
#define BATCH 256
#define TLEN  500
#define IDIM  1024
#define ODIM  2048
#define TEFF  (TLEN - 1)            // 499
#define MEFF  (BATCH * TEFF)

// ---------------- Tiling (R7-proven config) ----------------
#define BM 128
#define BN 128
#define BK 32
#define NST 4                       // B-pipeline depth (cp.async)
#define NITER (IDIM / BK)           // 32
#define NCHUNK 4                    // 128,128,128,115
#define ROWP  (BK + 8)              // padded row stride in halves (40)
#define ABUF_BYTES (BM * ROWP * 2)         // 10240 (fp16 A, double-buffered)
#define B_STAGE_BYTES (BN * ROWP * 2)      // 10240
#define B_BASE_OFF (2 * ABUF_BYTES)        // 20480
#define H_OFF   (B_BASE_OFF + NST * B_STAGE_BYTES)  // 61440
#define ROWPH 136                   // h-tile row stride in halves
#define SMEM_TOTAL (H_OFF + BM * ROWPH * 2)         // 96256

// ---------------- Scratch ----------------
__device__ __align__(256) __half g_Bh[(size_t)ODIM * IDIM];  // ~4 MB (L2-resident)

// ---------------- PTX helpers ----------------
__device__ __forceinline__ uint32_t smem_u32(const void* p) {
    uint32_t a;
    asm("{ .reg .u64 t; cvta.to.shared.u64 t, %1; cvt.u32.u64 %0, t; }" : "=r"(a) : "l"(p));
    return a;
}
__device__ __forceinline__ void cp_async16(uint32_t dst, const void* src) {
    asm volatile("cp.async.cg.shared.global [%0], [%1], 16;" :: "r"(dst), "l"(src));
}
__device__ __forceinline__ void cp_commit() {
    asm volatile("cp.async.commit_group;" ::: "memory");
}
__device__ __forceinline__ void sts64(uint32_t addr, uint32_t lo, uint32_t hi) {
    asm volatile("st.shared.v2.u32 [%0], {%1, %2};" :: "r"(addr), "r"(lo), "r"(hi) : "memory");
}
__device__ __forceinline__ void stg_cs(float* p, float v) {
    asm volatile("st.global.cs.f32 [%0], %1;" :: "l"(p), "f"(v) : "memory");
}
__device__ __forceinline__ void ldmatrix_x4(uint32_t& r0, uint32_t& r1, uint32_t& r2, uint32_t& r3,
                                            uint32_t addr) {
    asm volatile("ldmatrix.sync.aligned.m8n8.x4.shared.b16 {%0,%1,%2,%3}, [%4];"
                 : "=r"(r0), "=r"(r1), "=r"(r2), "=r"(r3) : "r"(addr));
}
__device__ __forceinline__ void mma_16816(float& c0, float& c1, float& c2, float& c3,
                                          uint32_t a0, uint32_t a1, uint32_t a2, uint32_t a3,
                                          uint32_t b0, uint32_t b1) {
    asm volatile(
        "mma.sync.aligned.m16n8k16.row.col.f32.f16.f16.f32 "
        "{%0,%1,%2,%3}, {%4,%5,%6,%7}, {%8,%9}, {%0,%1,%2,%3};"
        : "+f"(c0), "+f"(c1), "+f"(c2), "+f"(c3)
        : "r"(a0), "r"(a1), "r"(a2), "r"(a3), "r"(b0), "r"(b1));
}

// ---------------- w conversion (2 k's per thread, half2 store) ----------------
__global__ __launch_bounds__(256) void convert_w_kernel(const float* __restrict__ w) {
    const size_t idx = (size_t)blockIdx.x * 256 + threadIdx.x;   // n + kp*ODIM order
    const int n  = (int)(idx & (ODIM - 1));
    const int k  = (int)(idx >> 11) * 2;
    const float v0 = w[(size_t)k * ODIM + n];
    const float v1 = w[(size_t)(k + 1) * ODIM + n];
    __half2 h = __float22half2_rn(make_float2(v0, v1));
    *(__half2*)(g_Bh + (size_t)n * IDIM + k) = h;
}

// ---------------- Fused GEMM + scan ----------------
extern __shared__ __half smem[];

// A: predicated LDG.128 of fp32 x into registers (one K-stage: 128x32 fp32)
__device__ __forceinline__ void ldg_a(const float* __restrict__ x, int b, int t0, int rows,
                                      int k0, int tid, float4 (&v)[4]) {
#pragma unroll
    for (int q = 0; q < 4; q++) {
        const int f = q * 256 + tid;
        const int r = f >> 3, c = f & 7;
        float4 t = make_float4(0.f, 0.f, 0.f, 0.f);
        if (r < rows)
            t = *(const float4*)(x + ((size_t)(b * TLEN + t0 + r)) * IDIM + k0 + c * 4);
        v[q] = t;
    }
}
__device__ __forceinline__ void sts_a(uint32_t abuf, int tid, const float4 (&v)[4]) {
#pragma unroll
    for (int q = 0; q < 4; q++) {
        const int f = q * 256 + tid;
        const int r = f >> 3, c = f & 7;
        __half2 h0 = __float22half2_rn(make_float2(v[q].x, v[q].y));
        __half2 h1 = __float22half2_rn(make_float2(v[q].z, v[q].w));
        sts64(abuf + (r * ROWP + c * 4) * 2, *(uint32_t*)&h0, *(uint32_t*)&h1);
    }
}
__device__ __forceinline__ void load_b_stage(int tid, int n0, int kidx, int stage,
                                             uint32_t sbase) {
    const uint32_t sB = sbase + B_BASE_OFF + stage * B_STAGE_BYTES;
    const int k0 = kidx * BK;
#pragma unroll
    for (int q = 0; q < 2; q++) {
        int idx = tid + q * 256;
        int r = idx >> 2, c = idx & 3;
        const void* g = (const void*)(g_Bh + (size_t)(n0 + r) * IDIM + k0 + c * 8);
        cp_async16(sB + (r * ROWP + c * 8) * 2, g);
    }
}

__global__ __launch_bounds__(256, 2)
void synaptic_fused_kernel(const float* __restrict__ x,
                           float* __restrict__ out,
                           const float* __restrict__ alpha,
                           const float* __restrict__ beta) {
    const int tid = threadIdx.x;
    const int wid = tid >> 5;
    const int lane = tid & 31;
    const int warp_m = wid & 1;
    const int warp_n = wid >> 1;
    const int n0 = blockIdx.x * BN;
    const int b  = blockIdx.y;

    const uint32_t sbase = smem_u32(smem);
    __half* hs16 = (__half*)((char*)smem + H_OFF);

    float decay = 0.f, syn = 0.f;
    if (tid < BN) {
        const int o = n0 + tid;
        decay = alpha[o] * (1.0f - beta[o]);
    }

    const int lrow = lane & 15;
    const int lk   = (lane >> 4) * 8;
    const uint32_t a_lane = (uint32_t)((warp_m * 64 + lrow) * ROWP + lk) * 2;
    const uint32_t b_lane = (uint32_t)((warp_n * 32 + lrow) * ROWP + lk) * 2;
    const int r_lo = lane >> 2;
    const int c_lo = (lane & 3) * 2;

    float4 av[4];

    // ---- prologue for chunk 0 ----
    ldg_a(x, b, 0, BM, 0, tid, av);
    sts_a(sbase, tid, av);
#pragma unroll
    for (int s = 0; s < NST - 1; s++) {
        load_b_stage(tid, n0, s, s, sbase);
        cp_commit();
    }

    for (int ch = 0; ch < NCHUNK; ch++) {
        const int t0 = ch * BM;
        const int rows = (TEFF - t0 < BM) ? (TEFF - t0) : BM;  // 128,128,128,115

        float acc[4][4][4];
#pragma unroll
        for (int i = 0; i < 4; i++)
#pragma unroll
            for (int j = 0; j < 4; j++)
#pragma unroll
                for (int f = 0; f < 4; f++) acc[i][j][f] = 0.f;

        // ---- mainloop: ONE barrier per iteration ----
        for (int it = 0; it < NITER; it++) {
            const int s = it & (NST - 1);
            asm volatile("cp.async.wait_group %0;" :: "n"(NST - 2) : "memory");
            __syncthreads();

            if (it + 1 < NITER)
                ldg_a(x, b, t0, rows, (it + 1) * BK, tid, av);
            if (it + NST - 1 < NITER)
                load_b_stage(tid, n0, it + NST - 1, (it + NST - 1) & (NST - 1), sbase);
            cp_commit();

            const uint32_t sa = sbase + (it & 1) * ABUF_BYTES + a_lane;
            const uint32_t sb = sbase + B_BASE_OFF + s * B_STAGE_BYTES + b_lane;

#pragma unroll
            for (int kk = 0; kk < BK; kk += 16) {
                uint32_t a[4][4], bm[2][4];
#pragma unroll
                for (int mt = 0; mt < 4; mt++)
                    ldmatrix_x4(a[mt][0], a[mt][1], a[mt][2], a[mt][3],
                                sa + (mt * 16 * ROWP + kk) * 2);
#pragma unroll
                for (int np = 0; np < 2; np++)
                    ldmatrix_x4(bm[np][0], bm[np][1], bm[np][2], bm[np][3],
                                sb + (np * 16 * ROWP + kk) * 2);
#pragma unroll
                for (int mt = 0; mt < 4; mt++) {
#pragma unroll
                    for (int nt = 0; nt < 4; nt++) {
                        const int np = nt >> 1, odd = nt & 1;
                        mma_16816(acc[mt][nt][0], acc[mt][nt][1], acc[mt][nt][2], acc[mt][nt][3],
                                  a[mt][0], a[mt][1], a[mt][2], a[mt][3],
                                  bm[np][odd], bm[np][2 + odd]);
                    }
                }
            }

            if (it + 1 < NITER)
                sts_a(sbase + ((it + 1) & 1) * ABUF_BYTES, tid, av);
        }

        // ---- write h tile (fp16) to dedicated smem; no pipeline drain needed ----
#pragma unroll
        for (int mt = 0; mt < 4; mt++) {
#pragma unroll
            for (int half = 0; half < 2; half++) {
                const int row = warp_m * 64 + mt * 16 + r_lo + half * 8;
                __half* dst = hs16 + (size_t)row * ROWPH + warp_n * 32 + c_lo;
#pragma unroll
                for (int nt = 0; nt < 4; nt++) {
                    __half2 hv = __float22half2_rn(
                        make_float2(acc[mt][nt][half * 2 + 0], acc[mt][nt][half * 2 + 1]));
                    *(__half2*)(dst + nt * 8) = hv;
                }
            }
        }
        __syncthreads();   // h visible; pipeline buffers now free for next chunk

        // ---- issue next chunk's prologue BEFORE the scan (overlap DMA with scan) ----
        if (ch + 1 < NCHUNK) {
            const int nt0 = (ch + 1) * BM;
            const int nrows = (TEFF - nt0 < BM) ? (TEFF - nt0) : BM;
            ldg_a(x, b, nt0, nrows, 0, tid, av);
            sts_a(sbase, tid, av);
#pragma unroll
            for (int s = 0; s < NST - 1; s++) {
                load_b_stage(tid, n0, s, s, sbase);
                cp_commit();
            }
        }

        // ---- column-parallel scan (warps 0-3); others park at next barrier ----
        if (tid < BN) {
            float* obase = out + (size_t)b * TLEN * ODIM + n0 + tid;
            if (ch == 0) stg_cs(obase, 0.0f);
#pragma unroll 8
            for (int t = 0; t < rows; t++) {
                float h = __half2float(hs16[(size_t)t * ROWPH + tid]);
                syn = fmaf(decay, syn, h);
                stg_cs(obase + (size_t)(t0 + t + 1) * ODIM, syn);
            }
        }
        // no trailing barrier: next chunk's mainloop top barrier orders everything
    }
}

// ---------------- Launch ----------------
extern "C" void kernel_launch(void* const* d_in, const int* in_sizes, int n_in,
                              void* d_out, int out_size) {
    const float* x     = (const float*)d_in[0];
    const float* w     = (const float*)d_in[1];
    const float* alpha = (const float*)d_in[2];
    const float* beta  = (const float*)d_in[3];
    float* out = (float*)d_out;

    cudaFuncSetAttribute(synaptic_fused_kernel, cudaFuncAttributeMaxDynamicSharedMemorySize,
                         SMEM_TOTAL);

    convert_w_kernel<<<(IDIM * ODIM) / 512, 256>>>(w);
    synaptic_fused_kernel<<<dim3(ODIM / BN, BATCH), 256, SMEM_TOTAL>>>(x, out, alpha, beta);
}